// round 8
// baseline (speedup 1.0000x reference)
#include <cuda_runtime.h>
#include <cuda_bf16.h>

// 4096 possible 12-bit rows -> 32 floats each = 512 KB LUT in device global.
__device__ float g_lut[4096 * 32];
__device__ unsigned int g_done = 0;   // builder blocks completed
__device__ unsigned int g_exit = 0;   // blocks finished (counter reset)

#define THREADS  256
#define NWARPS   8
#define G        4          // 8-row groups per warp per iteration
#define GROUPS_PER_TILE (NWARPS * G)   // 32 groups = 256 rows per block-tile
#define NBUILD   64
#define PBLOCKS  1184

// ---- LUT build: one (b, s) item per thread ----
__device__ __forceinline__ void build_lut_item(int idx,
                                               const float* __restrict__ pat,
                                               const float* __restrict__ pos,
                                               const int*   __restrict__ conn)
{
    const int b = idx >> 2;
    const int s = idx & 3;

    const int bits3n = 3 * (s + 1);
    const int paddr  = b & ((1 << bits3n) - 1);   // last 3n columns, MSB-first

    float out[8];
    int pb = 0;
#pragma unroll
    for (int j = 0; j < 3; j++) {
        float v = __ldg(&pat[(s * 3 + j) * 4096 + paddr]);
        int bit = (v > 0.5f) ? 1 : 0;
        out[j]  = (float)bit;
        pb |= bit << j;
    }

    const int in_bits = bits3n + 3;
    const int nb      = (in_bits < 12) ? in_bits : 12;
#pragma unroll
    for (int k = 0; k < 5; k++) {
        int addr = 0;
        for (int j = 0; j < nb; j++) {
            int c   = __ldg(&conn[(s * 5 + k) * 12 + j]) % in_bits;
            int bit = (c < bits3n) ? ((paddr >> (bits3n - 1 - c)) & 1)
                                   : ((pb >> (c - bits3n)) & 1);
            addr |= bit << j;
        }
        out[3 + k] = __ldg(&pos[(s * 5 + k) * 4096 + addr]);
    }

    float4* dst = (float4*)&g_lut[b * 32 + s * 8];
    dst[0] = ((const float4*)out)[0];
    dst[1] = ((const float4*)out)[1];
}

// Persistent, warp-autonomous fused kernel. No smem staging, no per-tile bars.
// Per 8-row group (one warp): 3 coalesced input LDGs -> 3 ballots -> per-lane
// 12-bit extract (funnelshift+brev) -> shfl-broadcast -> 2 LDG.128 LUT gather
// -> 2 coalesced STG.128 streaming stores.
__global__ __launch_bounds__(THREADS)
void fused_kernel(const int* __restrict__ tb,
                  float* __restrict__ out,
                  int nrows,
                  const float* __restrict__ pat,
                  const float* __restrict__ pos,
                  const int*   __restrict__ conn)
{
    const int tid  = threadIdx.x;
    const int lane = tid & 31;
    const int wid  = tid >> 5;
    const int bid  = blockIdx.x;

    // ---- Builder role (once) ----
    if (bid < NBUILD) {
        build_lut_item(bid * THREADS + tid, pat, pos, conn);
        __syncthreads();
        if (tid == 0) {
            unsigned int one = 1u, ignored;
            asm volatile("atom.add.release.gpu.u32 %0, [%1], %2;"
                         : "=r"(ignored) : "l"(&g_done), "r"(one) : "memory");
        }
    }

    const int ngroups = nrows >> 3;                       // full 8-row groups
    const int ntiles  = (ngroups + GROUPS_PER_TILE - 1) / GROUPS_PER_TILE;

    float4* out4 = (float4*)out;
    bool need_gate = true;

    for (int tile = bid; tile < ntiles; tile += gridDim.x) {
        const int gbase = tile * GROUPS_PER_TILE + wid * G;
        const int ng    = min(G, ngroups - gbase);        // warp-uniform

        // 1) Input loads: up to 12 independent coalesced LDGs.
        int v[G][3];
#pragma unroll
        for (int g = 0; g < G; g++) {
            if (g < ng) {
                const int* p = tb + (size_t)(gbase + g) * 96 + lane;
                v[g][0] = __ldcs(p);
                v[g][1] = __ldcs(p + 32);
                v[g][2] = __ldcs(p + 64);
            }
        }

        // 2) Ballot-pack 96 bits/group into 3 registers, then per-lane extract.
        unsigned bal[G][3];
#pragma unroll
        for (int g = 0; g < G; g++) {
            if (g < ng) {
                bal[g][0] = __ballot_sync(0xffffffffu, v[g][0]);
                bal[g][1] = __ballot_sync(0xffffffffu, v[g][1]);
                bal[g][2] = __ballot_sync(0xffffffffu, v[g][2]);
            }
        }

        // lanes 0..7 hold row (lane)'s LUT index; others mirror lane&7 (unused).
        int idxv[G];
        {
            const int r = lane & 7;
            const int p = 12 * r;            // 0,12,24,36,48,60,72,84
            const int w = p >> 5;
#pragma unroll
            for (int g = 0; g < G; g++) {
                if (g < ng) {
                    unsigned lo = (w == 0) ? bal[g][0] : (w == 1) ? bal[g][1] : bal[g][2];
                    unsigned hi = (w == 0) ? bal[g][1] : (w == 1) ? bal[g][2] : 0u;
                    unsigned f  = __funnelshift_r(lo, hi, p & 31) & 0xFFFu;
                    idxv[g] = (int)(__brev(f) >> 20);   // MSB-first 12-bit value
                }
            }
        }

        // ---- LUT gate (first iteration only): two-phase acquire ----
        if (need_gate) {
            if (tid == 0) {
                unsigned int d;
                do {
                    asm volatile("ld.acquire.gpu.u32 %0, [%1];"
                                 : "=r"(d) : "l"(&g_done) : "memory");
                    if (d >= NBUILD) break;
                    __nanosleep(64);
                } while (true);
            }
            __syncthreads();
            need_gate = false;
        }

        // 3) LUT gather: 2 LDG.128 per lane per group (all issued before stores).
        const int chunk = lane & 7;
        float4 d[G][2];
#pragma unroll
        for (int g = 0; g < G; g++) {
            if (g < ng) {
#pragma unroll
                for (int j = 0; j < 2; j++) {
                    const int row = j * 4 + (lane >> 3);  // (j*32+lane)>>3
                    const int rid = __shfl_sync(0xffffffffu, idxv[g], row);
                    d[g][j] = __ldg((const float4*)&g_lut[rid * 32] + chunk);
                }
            }
        }

        // 4) Coalesced streaming stores: 64 float4 per group.
#pragma unroll
        for (int g = 0; g < G; g++) {
            if (g < ng) {
                float4* o = out4 + (size_t)(gbase + g) * 64;
                __stcs(&o[lane], d[g][0]);
                __stcs(&o[32 + lane], d[g][1]);
            }
        }
    }

    // ---- Tail rows (nrows % 8), handled scalar by block 0 (post-gate) ----
    const int rem = nrows & 7;
    if (rem && bid == 0 && tid < rem) {
        const int row = ngroups * 8 + tid;
        int b = 0;
#pragma unroll
        for (int c = 0; c < 12; c++)
            b |= (tb[(size_t)row * 12 + c] != 0) << (11 - c);
        const float4* lut = (const float4*)&g_lut[b * 32];
        float4* o = out4 + (size_t)row * 8;
#pragma unroll
        for (int c = 0; c < 8; c++)
            o[c] = __ldg(&lut[c]);
    }

    // ---- Exit accounting: last block resets counters for next replay ----
    if (tid == 0) {
        unsigned int t = atomicAdd(&g_exit, 1u);
        if (t == gridDim.x - 1) {
            g_done = 0;     // visible at kernel-completion boundary
            g_exit = 0;
        }
    }
}

extern "C" void kernel_launch(void* const* d_in, const int* in_sizes, int n_in,
                              void* d_out, int out_size)
{
    const int*   tb   = (const int*)  d_in[0];  // type_bits      (B, 12) i32
    const float* pat  = (const float*)d_in[1];  // pattern_tables (4,3,4096) f32
    const float* pos  = (const float*)d_in[2];  // position_tables(4,5,4096) f32
    const int*   conn = (const int*)  d_in[3];  // position_conn  (4,5,12) i32
    float*       out  = (float*)d_out;          // (B, 4, 8) f32

    int nrows = in_sizes[0] / 12;

    fused_kernel<<<PBLOCKS, THREADS>>>(tb, out, nrows, pat, pos, conn);
}